// round 3
// baseline (speedup 1.0000x reference)
#include <cuda_runtime.h>
#include <math.h>

#define BB 8
#define SS 256
#define NTT 50
#define EE 64

__device__ double g_ll;
__device__ float g_intenT[BB];

__device__ __forceinline__ float softplus_f(float x) {
    return fmaxf(x, 0.0f) + log1pf(__expf(-fabsf(x)));
}

__device__ __forceinline__ float read_T(const void* p) {
    int v = *(const int*)p;
    if (v > 0 && v < (1 << 26)) return (float)v;   // int32 / low half of int64
    return *(const float*)p;                        // float32 fallback
}

__global__ void init_k() {
    if (threadIdx.x == 0) g_ll = 0.0;
    if (threadIdx.x < BB) g_intenT[threadIdx.x] = 0.0f;
}

// Part 1: per (b,i) block. 128 threads = 2 j-slices x 64 e-lanes.
__global__ void part1_k(const float* __restrict__ times, const int* __restrict__ types,
                        const float* __restrict__ emb, const float* __restrict__ a,
                        const float* __restrict__ Amat, const float* __restrict__ Pmat) {
    __shared__ float s_t[SS];
    __shared__ int   s_ty[SS];
    __shared__ float s_emb[NTT * EE];
    __shared__ float s_part[128];
    __shared__ float s_red[2];

    const int b = blockIdx.x / SS;
    const int i = blockIdx.x % SS;
    const int tid = threadIdx.x;
    const int e = tid & 63;
    const int half = tid >> 6;

    for (int j = tid; j < SS; j += 128) { s_t[j] = times[b * SS + j]; s_ty[j] = types[b * SS + j]; }
    for (int j = tid; j < NTT * EE; j += 128) s_emb[j] = emb[j];
    __syncthreads();

    const float ti = s_t[i];
    const int tyi = s_ty[i];
    const float ei = s_emb[tyi * EE + e];

    float m = 0.0f;
    #pragma unroll 4
    for (int j = half; j < i; j += 2) {
        const float tj = s_t[j];
        const int tyj = s_ty[j];
        const float ej = s_emb[tyj * EE + e];
        const int base = (tyj * NTT + tyi) * EE + e;
        const float Av = __ldg(&Amat[base]);
        const float Pv = __ldg(&Pmat[base]);
        const float g = ei * ej;
        const float dec = __expf(-g * Pv * (ti - tj));
        m = fmaf(g * Av, dec, m);
    }
    s_part[tid] = m;
    __syncthreads();

    if (tid < 64) {
        float mt = s_part[e] + s_part[64 + e];
        float x = fmaf(ei, a[tyi * EE + e], mt);
        float sp = softplus_f(x);
        #pragma unroll
        for (int off = 16; off > 0; off >>= 1)
            sp += __shfl_xor_sync(0xffffffffu, sp, off);
        if ((e & 31) == 0) s_red[e >> 5] = sp;
    }
    __syncthreads();

    if (tid == 0 && ti >= 0.0f) {
        float inten = s_red[0] + s_red[1];
        atomicAdd(&g_ll, (double)logf(inten + 1e-16f));
    }
}

// Part 2: per (b,k) block. 256 threads = 4 i-slices x 64 e-lanes.
__global__ void part2_k(const float* __restrict__ times, const int* __restrict__ types,
                        const float* __restrict__ emb, const float* __restrict__ a,
                        const float* __restrict__ Amat, const float* __restrict__ Pmat,
                        const void* __restrict__ Tp) {
    __shared__ float s_t[SS];
    __shared__ int   s_ty[SS];
    __shared__ float s_emb[NTT * EE];
    __shared__ float s_part[256];
    __shared__ float s_red[2];

    const int b = blockIdx.x / NTT;
    const int k = blockIdx.x % NTT;
    const int tid = threadIdx.x;
    const int e = tid & 63;
    const int slice = tid >> 6;

    for (int j = tid; j < SS; j += 256) { s_t[j] = times[b * SS + j]; s_ty[j] = types[b * SS + j]; }
    for (int j = tid; j < NTT * EE; j += 256) s_emb[j] = emb[j];
    __syncthreads();

    const float Tf = read_T(Tp);
    const float ek = s_emb[k * EE + e];

    float mT = 0.0f;
    #pragma unroll 4
    for (int i = slice; i < SS; i += 4) {
        const float ti = s_t[i];
        if (ti < 0.0f) continue;
        const int tyi = s_ty[i];
        const float ev = s_emb[tyi * EE + e];
        const int base = (tyi * NTT + k) * EE + e;
        const float Av = __ldg(&Amat[base]);
        const float Pv = __ldg(&Pmat[base]);
        const float g = ek * ev;
        const float dec = __expf(-g * Pv * (Tf - ti));
        mT = fmaf(g * Av, dec, mT);
    }
    s_part[tid] = mT;
    __syncthreads();

    if (tid < 64) {
        float m = s_part[e] + s_part[64 + e] + s_part[128 + e] + s_part[192 + e];
        float x = fmaf(ek, a[k * EE + e], m);
        float sp = softplus_f(x);
        #pragma unroll
        for (int off = 16; off > 0; off >>= 1)
            sp += __shfl_xor_sync(0xffffffffu, sp, off);
        if ((e & 31) == 0) s_red[e >> 5] = sp;
    }
    __syncthreads();

    if (tid == 0) atomicAdd(&g_intenT[b], s_red[0] + s_red[1]);
}

// Final: base_sum, per-batch first/last/any, combine to scalar.
__global__ void final_k(const float* __restrict__ times, const void* __restrict__ Tp,
                        const float* __restrict__ emb, const float* __restrict__ a,
                        float* __restrict__ out) {
    __shared__ float s_red[8];
    __shared__ float s_first[BB], s_last[BB];
    __shared__ int s_any[BB];

    const int tid = threadIdx.x;  // 256 threads

    float ps = 0.0f;
    for (int idx = tid; idx < NTT * EE; idx += 256)
        ps += softplus_f(emb[idx] * a[idx]);
    #pragma unroll
    for (int off = 16; off > 0; off >>= 1)
        ps += __shfl_xor_sync(0xffffffffu, ps, off);
    if ((tid & 31) == 0) s_red[tid >> 5] = ps;

    if (tid < BB) {
        float first = 1e30f, last = -1e30f;
        int any = 0;
        for (int i = 0; i < SS; i++) {
            float t = times[tid * SS + i];
            if (t >= 0.0f) { any = 1; first = fminf(first, t); last = fmaxf(last, t); }
        }
        s_any[tid] = any;
        s_first[tid] = any ? first : 0.0f;
        s_last[tid] = any ? last : 0.0f;
    }
    __syncthreads();

    if (tid == 0) {
        float base_sum = 0.0f;
        #pragma unroll
        for (int w = 0; w < 8; w++) base_sum += s_red[w];
        const float Tf = read_T(Tp);
        double integral = 0.0;
        for (int b = 0; b < BB; b++) {
            float ib;
            if (s_any[b]) ib = g_intenT[b] * (Tf - s_last[b]) + base_sum * s_first[b];
            else          ib = base_sum * Tf;
            integral += (double)ib;
        }
        out[0] = (float)(-(g_ll - integral));
    }
}

extern "C" void kernel_launch(void* const* d_in, const int* in_sizes, int n_in,
                              void* d_out, int out_size) {
    const float* times = (const float*)d_in[0];
    const int*   types = (const int*)d_in[1];
    const void*  Tp    = d_in[2];
    const float* emb   = (const float*)d_in[3];
    const float* a     = (const float*)d_in[4];
    const float* Amat  = (const float*)d_in[5];
    const float* Pmat  = (const float*)d_in[6];
    float* out = (float*)d_out;

    init_k<<<1, 32>>>();
    part1_k<<<BB * SS, 128>>>(times, types, emb, a, Amat, Pmat);
    part2_k<<<BB * NTT, 256>>>(times, types, emb, a, Amat, Pmat, Tp);
    final_k<<<1, 256>>>(times, Tp, emb, a, out);
}

// round 4
// speedup vs baseline: 1.3859x; 1.3859x over previous
#include <cuda_runtime.h>
#include <math.h>

#define BB 8
#define SS 256
#define NTT 50
#define EE 64

#define P1_BLOCKS (BB * 64)          // 512: 4 balanced rows each
#define P2_BLOCKS (BB * NTT)         // 400: one (b,k) each

__device__ double g_ll;
__device__ float g_intenT[BB];

__device__ __forceinline__ float softplus_f(float x) {
    return fmaxf(x, 0.0f) + log1pf(__expf(-fabsf(x)));
}

__device__ __forceinline__ float read_T(const void* p) {
    int v = *(const int*)p;
    if (v > 0 && v < (1 << 26)) return (float)v;   // int32 / low half of int64
    return *(const float*)p;                        // float32 fallback
}

__global__ void init_k() {
    if (threadIdx.x == 0) g_ll = 0.0;
    if (threadIdx.x < BB) g_intenT[threadIdx.x] = 0.0f;
}

// Fused body: blocks [0,512) do part1 (4 balanced rows each),
//             blocks [512,912) do part2 (one (b,k) each).
// 256 threads = 4 j/i-slices x 64 e-lanes.
__global__ __launch_bounds__(256) void body_k(
        const float* __restrict__ times, const int* __restrict__ types,
        const float* __restrict__ emb, const float* __restrict__ a,
        const float* __restrict__ Amat, const float* __restrict__ Pmat,
        const void* __restrict__ Tp) {
    __shared__ float s_t[SS];
    __shared__ int   s_ty[SS];
    __shared__ float s_emb[NTT * EE];
    __shared__ float sA[NTT * EE];
    __shared__ float sP[NTT * EE];
    __shared__ float s_part[256];
    __shared__ float s_red[2];

    const int tid = threadIdx.x;
    const int e = tid & 63;
    const int slice = tid >> 6;
    const int lane = tid & 31;

    if (blockIdx.x < P1_BLOCKS) {
        // ---------------- part 1: log-likelihood ----------------
        const int b = blockIdx.x >> 6;
        const int grp = blockIdx.x & 63;

        for (int j = tid; j < SS; j += 256) {
            s_t[j] = times[b * SS + j];
            s_ty[j] = types[b * SS + j];
        }
        for (int j = tid; j < NTT * EE; j += 256) s_emb[j] = emb[j];
        __syncthreads();

        double ll_acc = 0.0;
        const int rows[4] = {2 * grp, 2 * grp + 1, 255 - 2 * grp, 254 - 2 * grp};

        #pragma unroll
        for (int r = 0; r < 4; r++) {
            const int i = rows[r];
            const int tyi = s_ty[i];
            const float ti = s_t[i];

            // stage A[:, tyi, :] and P[:, tyi, :] (50x64 each) into smem
            for (int idx = tid; idx < NTT * EE; idx += 256) {
                const int u = idx >> 6;
                const int gidx = (u * NTT + tyi) * EE + (idx & 63);
                sA[idx] = __ldg(&Amat[gidx]);
                sP[idx] = __ldg(&Pmat[gidx]);
            }
            __syncthreads();

            const float ei = s_emb[tyi * EE + e];
            float m = 0.0f;
            #pragma unroll 4
            for (int j = slice; j < i; j += 4) {
                const int tyj = s_ty[j];
                const float ej = s_emb[tyj * EE + e];
                const float Av = sA[tyj * EE + e];
                const float Pv = sP[tyj * EE + e];
                const float g = ei * ej;
                const float dec = __expf(-g * Pv * (ti - s_t[j]));
                m = fmaf(g * Av, dec, m);
            }
            s_part[tid] = m;
            __syncthreads();

            if (tid < 64) {
                float mt = s_part[e] + s_part[64 + e] + s_part[128 + e] + s_part[192 + e];
                float x = fmaf(ei, __ldg(&a[tyi * EE + e]), mt);
                float sp = softplus_f(x);
                #pragma unroll
                for (int off = 16; off > 0; off >>= 1)
                    sp += __shfl_xor_sync(0xffffffffu, sp, off);
                if (lane == 0) s_red[e >> 5] = sp;
            }
            __syncthreads();

            if (tid == 0 && ti >= 0.0f)
                ll_acc += (double)logf(s_red[0] + s_red[1] + 1e-16f);
        }
        if (tid == 0) atomicAdd(&g_ll, ll_acc);
    } else {
        // ---------------- part 2: integral intensity at T ----------------
        const int idx2 = blockIdx.x - P1_BLOCKS;
        const int b = idx2 / NTT;
        const int k = idx2 % NTT;

        for (int j = tid; j < SS; j += 256) {
            s_t[j] = times[b * SS + j];
            s_ty[j] = types[b * SS + j];
        }
        for (int j = tid; j < NTT * EE; j += 256) s_emb[j] = emb[j];
        // stage A[:, k, :] and P[:, k, :]
        for (int idx = tid; idx < NTT * EE; idx += 256) {
            const int u = idx >> 6;
            const int gidx = (u * NTT + k) * EE + (idx & 63);
            sA[idx] = __ldg(&Amat[gidx]);
            sP[idx] = __ldg(&Pmat[gidx]);
        }
        __syncthreads();

        const float Tf = read_T(Tp);
        const float ek = s_emb[k * EE + e];

        float mT = 0.0f;
        #pragma unroll 4
        for (int i = slice; i < SS; i += 4) {
            const float ti = s_t[i];
            if (ti < 0.0f) continue;
            const int tyi = s_ty[i];
            const float ev = s_emb[tyi * EE + e];
            const float Av = sA[tyi * EE + e];
            const float Pv = sP[tyi * EE + e];
            const float g = ek * ev;
            const float dec = __expf(-g * Pv * (Tf - ti));
            mT = fmaf(g * Av, dec, mT);
        }
        s_part[tid] = mT;
        __syncthreads();

        if (tid < 64) {
            float m = s_part[e] + s_part[64 + e] + s_part[128 + e] + s_part[192 + e];
            float x = fmaf(ek, __ldg(&a[k * EE + e]), m);
            float sp = softplus_f(x);
            #pragma unroll
            for (int off = 16; off > 0; off >>= 1)
                sp += __shfl_xor_sync(0xffffffffu, sp, off);
            if (lane == 0) s_red[e >> 5] = sp;
        }
        __syncthreads();

        if (tid == 0) atomicAdd(&g_intenT[b], s_red[0] + s_red[1]);
    }
}

// Final: base_sum (parallel), per-batch first/last/any (warp per batch), combine.
__global__ void final_k(const float* __restrict__ times, const void* __restrict__ Tp,
                        const float* __restrict__ emb, const float* __restrict__ a,
                        float* __restrict__ out) {
    __shared__ float s_red[8];
    __shared__ float s_first[BB], s_last[BB];
    __shared__ int s_any[BB];

    const int tid = threadIdx.x;   // 256 threads
    const int w = tid >> 5;        // warp = batch
    const int lane = tid & 31;

    // base_sum partial
    float ps = 0.0f;
    for (int idx = tid; idx < NTT * EE; idx += 256)
        ps += softplus_f(emb[idx] * a[idx]);
    #pragma unroll
    for (int off = 16; off > 0; off >>= 1)
        ps += __shfl_xor_sync(0xffffffffu, ps, off);
    if (lane == 0) s_red[w] = ps;

    // warp w scans batch w: 8 strided loads per lane
    {
        float mn = 1e30f, mx = -1e30f;
        int any = 0;
        #pragma unroll
        for (int m = 0; m < SS / 32; m++) {
            float t = times[w * SS + lane + 32 * m];
            if (t >= 0.0f) { any = 1; mn = fminf(mn, t); mx = fmaxf(mx, t); }
        }
        #pragma unroll
        for (int off = 16; off > 0; off >>= 1) {
            mn = fminf(mn, __shfl_xor_sync(0xffffffffu, mn, off));
            mx = fmaxf(mx, __shfl_xor_sync(0xffffffffu, mx, off));
            any |= __shfl_xor_sync(0xffffffffu, any, off);
        }
        if (lane == 0) {
            s_any[w] = any;
            s_first[w] = any ? mn : 0.0f;
            s_last[w] = any ? mx : 0.0f;
        }
    }
    __syncthreads();

    if (tid == 0) {
        float base_sum = 0.0f;
        #pragma unroll
        for (int ww = 0; ww < 8; ww++) base_sum += s_red[ww];
        const float Tf = read_T(Tp);
        double integral = 0.0;
        for (int b = 0; b < BB; b++) {
            float ib;
            if (s_any[b]) ib = g_intenT[b] * (Tf - s_last[b]) + base_sum * s_first[b];
            else          ib = base_sum * Tf;
            integral += (double)ib;
        }
        out[0] = (float)(-(g_ll - integral));
    }
}

extern "C" void kernel_launch(void* const* d_in, const int* in_sizes, int n_in,
                              void* d_out, int out_size) {
    const float* times = (const float*)d_in[0];
    const int*   types = (const int*)d_in[1];
    const void*  Tp    = d_in[2];
    const float* emb   = (const float*)d_in[3];
    const float* a     = (const float*)d_in[4];
    const float* Amat  = (const float*)d_in[5];
    const float* Pmat  = (const float*)d_in[6];
    float* out = (float*)d_out;

    init_k<<<1, 32>>>();
    body_k<<<P1_BLOCKS + P2_BLOCKS, 256>>>(times, types, emb, a, Amat, Pmat, Tp);
    final_k<<<1, 256>>>(times, Tp, emb, a, out);
}

// round 9
// speedup vs baseline: 1.7337x; 1.2510x over previous
#include <cuda_runtime.h>
#include <math.h>

#define BB 8
#define SS 256
#define NTT 50
#define EE 64

#define P1_BLOCKS (BB * 64)          // 512: 4 balanced rows each
#define P2_BLOCKS (BB * NTT)         // 400: one (b,k) each
#define GRID (P1_BLOCKS + P2_BLOCKS) // 912

__device__ unsigned g_count = 0;              // reset by last block each call
__device__ double g_ll_part[P1_BLOCKS];
__device__ float  g_int_part[P2_BLOCKS];

__device__ __forceinline__ float ex2f(float x) {
    float y;
    asm("ex2.approx.ftz.f32 %0, %1;" : "=f"(y) : "f"(x));
    return y;
}

__device__ __forceinline__ float softplus_f(float x) {
    return fmaxf(x, 0.0f) + log1pf(__expf(-fabsf(x)));
}

__device__ __forceinline__ float read_T(const void* p) {
    int v = *(const int*)p;
    if (v > 0 && v < (1 << 26)) return (float)v;   // int32 / low half of int64
    return *(const float*)p;                        // float32 fallback
}

#define LOG2E 1.4426950408889634f

__global__ __launch_bounds__(256) void body_k(
        const float* __restrict__ times, const int* __restrict__ types,
        const float* __restrict__ emb, const float* __restrict__ a,
        const float* __restrict__ Amat, const float* __restrict__ Pmat,
        const void* __restrict__ Tp, float* __restrict__ out) {
    __shared__ __align__(16) float s_emb[NTT * EE];
    __shared__ __align__(16) float sAe[NTT * EE];
    __shared__ __align__(16) float sPe[NTT * EE];
    __shared__ float s_t[SS];
    __shared__ int   s_tyo[SS];      // type * EE
    __shared__ float s_part[256];
    __shared__ float s_red[8];
    __shared__ int   s_last;

    const int tid = threadIdx.x;
    const int e = tid & 63;
    const int slice = tid >> 6;
    const int lane = tid & 31;
    const int w = tid >> 5;

    const float4* __restrict__ emb4 = (const float4*)emb;
    const float4* __restrict__ A4 = (const float4*)Amat;
    const float4* __restrict__ P4 = (const float4*)Pmat;
    float4* s_emb4 = (float4*)s_emb;
    float4* sAe4 = (float4*)sAe;
    float4* sPe4 = (float4*)sPe;

    if (blockIdx.x < P1_BLOCKS) {
        // ---------------- part 1: log-likelihood ----------------
        const int b = blockIdx.x >> 6;
        const int grp = blockIdx.x & 63;

        for (int j = tid; j < SS; j += 256) {
            s_t[j] = times[b * SS + j];
            s_tyo[j] = types[b * SS + j] * EE;
        }
        for (int idx4 = tid; idx4 < NTT * EE / 4; idx4 += 256)
            s_emb4[idx4] = emb4[idx4];
        __syncthreads();

        double ll_acc = 0.0;
        const int rows[4] = {2 * grp, 2 * grp + 1, 255 - 2 * grp, 254 - 2 * grp};

        #pragma unroll
        for (int r = 0; r < 4; r++) {
            const int i = rows[r];
            const int tyio = s_tyo[i];
            const float ti = s_t[i];

            // stage sAe = e_u * A[u, tyi, :], sPe = e_u * P[u, tyi, :]  (float4)
            const int tyi = tyio >> 6;  // EE = 64
            for (int idx4 = tid; idx4 < NTT * EE / 4; idx4 += 256) {
                const int u = idx4 >> 4;           // EE/4 = 16
                const int rm = idx4 & 15;
                const int g4 = (u * NTT + tyi) * 16 + rm;
                const float4 ev = s_emb4[idx4];
                float4 av = __ldg(&A4[g4]);
                float4 pv = __ldg(&P4[g4]);
                av.x *= ev.x; av.y *= ev.y; av.z *= ev.z; av.w *= ev.w;
                pv.x *= ev.x; pv.y *= ev.y; pv.z *= ev.z; pv.w *= ev.w;
                sAe4[idx4] = av;
                sPe4[idx4] = pv;
            }
            __syncthreads();

            const float ei = s_emb[tyio + e];
            const float k1 = -ei * LOG2E;
            float m0 = 0.0f, m1 = 0.0f;
            #pragma unroll 4
            for (int j = slice; j < i; j += 8) {
                const int o = s_tyo[j] + e;
                m0 = fmaf(sAe[o], ex2f(k1 * sPe[o] * (ti - s_t[j])), m0);
                const int j2 = j + 4;
                if (j2 < i) {
                    const int o2 = s_tyo[j2] + e;
                    m1 = fmaf(sAe[o2], ex2f(k1 * sPe[o2] * (ti - s_t[j2])), m1);
                }
            }
            s_part[tid] = m0 + m1;
            __syncthreads();

            if (tid < 64) {
                float mt = ei * (s_part[e] + s_part[64 + e] + s_part[128 + e] + s_part[192 + e]);
                float x = fmaf(ei, __ldg(&a[tyio + e]), mt);
                float sp = softplus_f(x);
                #pragma unroll
                for (int off = 16; off > 0; off >>= 1)
                    sp += __shfl_xor_sync(0xffffffffu, sp, off);
                if (lane == 0) s_red[e >> 5] = sp;
            }
            __syncthreads();

            if (tid == 0 && ti >= 0.0f)
                ll_acc += (double)logf(s_red[0] + s_red[1] + 1e-16f);
        }
        if (tid == 0) g_ll_part[blockIdx.x] = ll_acc;
    } else {
        // ---------------- part 2: intensity at T ----------------
        const int idx2 = blockIdx.x - P1_BLOCKS;
        const int b = idx2 / NTT;
        const int k = idx2 - b * NTT;

        for (int j = tid; j < SS; j += 256) {
            s_t[j] = times[b * SS + j];
            s_tyo[j] = types[b * SS + j] * EE;
        }
        for (int idx4 = tid; idx4 < NTT * EE / 4; idx4 += 256) {
            s_emb4[idx4] = emb4[idx4];
        }
        __syncthreads();
        for (int idx4 = tid; idx4 < NTT * EE / 4; idx4 += 256) {
            const int u = idx4 >> 4;
            const int rm = idx4 & 15;
            const int g4 = (u * NTT + k) * 16 + rm;
            const float4 ev = s_emb4[idx4];
            float4 av = __ldg(&A4[g4]);
            float4 pv = __ldg(&P4[g4]);
            av.x *= ev.x; av.y *= ev.y; av.z *= ev.z; av.w *= ev.w;
            pv.x *= ev.x; pv.y *= ev.y; pv.z *= ev.z; pv.w *= ev.w;
            sAe4[idx4] = av;
            sPe4[idx4] = pv;
        }
        __syncthreads();

        const float Tf = read_T(Tp);
        const float ek = s_emb[k * EE + e];
        const float k1 = -ek * LOG2E;

        float m0 = 0.0f, m1 = 0.0f;
        #pragma unroll 4
        for (int i = slice; i < SS; i += 8) {
            const float ti = s_t[i];
            if (ti >= 0.0f) {
                const int o = s_tyo[i] + e;
                m0 = fmaf(sAe[o], ex2f(k1 * sPe[o] * (Tf - ti)), m0);
            }
            const int i2 = i + 4;
            const float ti2 = s_t[i2];
            if (ti2 >= 0.0f) {
                const int o2 = s_tyo[i2] + e;
                m1 = fmaf(sAe[o2], ex2f(k1 * sPe[o2] * (Tf - ti2)), m1);
            }
        }
        s_part[tid] = m0 + m1;
        __syncthreads();

        if (tid < 64) {
            float m = ek * (s_part[e] + s_part[64 + e] + s_part[128 + e] + s_part[192 + e]);
            float x = fmaf(ek, __ldg(&a[k * EE + e]), m);
            float sp = softplus_f(x);
            #pragma unroll
            for (int off = 16; off > 0; off >>= 1)
                sp += __shfl_xor_sync(0xffffffffu, sp, off);
            if (lane == 0) s_red[e >> 5] = sp;
        }
        __syncthreads();

        if (tid == 0) g_int_part[idx2] = s_red[0] + s_red[1];
    }

    // ---------------- last block finishes ----------------
    if (tid == 0) {
        __threadfence();
        unsigned ticket = atomicAdd(&g_count, 1u);
        s_last = (ticket == GRID - 1);
    }
    __syncthreads();
    if (!s_last) return;

    // base_sum partials (deterministic tree)
    {
        float ps = 0.0f;
        for (int idx = tid; idx < NTT * EE; idx += 256)
            ps += softplus_f(emb[idx] * a[idx]);
        #pragma unroll
        for (int off = 16; off > 0; off >>= 1)
            ps += __shfl_xor_sync(0xffffffffu, ps, off);
        if (lane == 0) s_red[w] = ps;
    }

    // ll sum: 512 doubles
    __shared__ double s_dll[8];
    {
        double d = g_ll_part[tid] + g_ll_part[tid + 256];
        #pragma unroll
        for (int off = 16; off > 0; off >>= 1)
            d += __shfl_xor_sync(0xffffffffu, d, off);
        if (lane == 0) s_dll[w] = d;
    }

    // per-batch intensity-at-T sum + first/last/any scan (warp per batch)
    __shared__ float s_int[BB], s_first[BB], s_last_t[BB];
    __shared__ int s_any[BB];
    {
        float iv = 0.0f;
        if (lane < NTT) iv += g_int_part[w * NTT + lane];
        if (lane + 32 < NTT) iv += g_int_part[w * NTT + lane + 32];
        float mn = 1e30f, mx = -1e30f;
        int any = 0;
        #pragma unroll
        for (int mloop = 0; mloop < SS / 32; mloop++) {
            float t = times[w * SS + lane + 32 * mloop];
            if (t >= 0.0f) { any = 1; mn = fminf(mn, t); mx = fmaxf(mx, t); }
        }
        #pragma unroll
        for (int off = 16; off > 0; off >>= 1) {
            iv += __shfl_xor_sync(0xffffffffu, iv, off);
            mn = fminf(mn, __shfl_xor_sync(0xffffffffu, mn, off));
            mx = fmaxf(mx, __shfl_xor_sync(0xffffffffu, mx, off));
            any |= __shfl_xor_sync(0xffffffffu, any, off);
        }
        if (lane == 0) {
            s_int[w] = iv;
            s_any[w] = any;
            s_first[w] = any ? mn : 0.0f;
            s_last_t[w] = any ? mx : 0.0f;
        }
    }
    __syncthreads();

    if (tid == 0) {
        float base_sum = 0.0f;
        double ll = 0.0;
        #pragma unroll
        for (int ww = 0; ww < 8; ww++) { base_sum += s_red[ww]; ll += s_dll[ww]; }
        const float Tf = read_T(Tp);
        double integral = 0.0;
        for (int b = 0; b < BB; b++) {
            float ib;
            if (s_any[b]) ib = s_int[b] * (Tf - s_last_t[b]) + base_sum * s_first[b];
            else          ib = base_sum * Tf;
            integral += (double)ib;
        }
        out[0] = (float)(-(ll - integral));
        g_count = 0;   // reset for next graph replay (deterministic)
    }
}

extern "C" void kernel_launch(void* const* d_in, const int* in_sizes, int n_in,
                              void* d_out, int out_size) {
    const float* times = (const float*)d_in[0];
    const int*   types = (const int*)d_in[1];
    const void*  Tp    = d_in[2];
    const float* emb   = (const float*)d_in[3];
    const float* a     = (const float*)d_in[4];
    const float* Amat  = (const float*)d_in[5];
    const float* Pmat  = (const float*)d_in[6];
    float* out = (float*)d_out;

    body_k<<<GRID, 256>>>(times, types, emb, a, Amat, Pmat, Tp, out);
}

// round 10
// speedup vs baseline: 1.8727x; 1.0801x over previous
#include <cuda_runtime.h>
#include <math.h>

#define BB 8
#define SS 256
#define NTT 50
#define EE 64

#define P1_BLOCKS (BB * 64)          // 512: 4 balanced rows each
#define P2_BLOCKS (BB * NTT)         // 400: one (b,k) each
#define GRID (P1_BLOCKS + P2_BLOCKS) // 912

__device__ unsigned g_count = 0;              // reset by last block each call
__device__ double g_ll_part[P1_BLOCKS];
__device__ float  g_int_part[P2_BLOCKS];

__device__ __forceinline__ float ex2f(float x) {
    float y;
    asm("ex2.approx.ftz.f32 %0, %1;" : "=f"(y) : "f"(x));
    return y;
}

__device__ __forceinline__ float softplus_f(float x) {
    return fmaxf(x, 0.0f) + log1pf(__expf(-fabsf(x)));
}

__device__ __forceinline__ float read_T(const void* p) {
    int v = *(const int*)p;
    if (v > 0 && v < (1 << 26)) return (float)v;   // int32 / low half of int64
    return *(const float*)p;                        // float32 fallback
}

#define LOG2E 1.4426950408889634f

__global__ __launch_bounds__(256, 6) void body_k(
        const float* __restrict__ times, const int* __restrict__ types,
        const float* __restrict__ emb, const float* __restrict__ a,
        const float* __restrict__ Amat, const float* __restrict__ Pmat,
        const void* __restrict__ Tp, float* __restrict__ out) {
    // s_ap[u*EE + e] = { e_u[e]*A[u,ty,e],  -LOG2E*e_row[e]*e_u[e]*P[u,ty,e] }
    __shared__ __align__(16) float2 s_ap[NTT * EE];
    __shared__ __align__(16) float2 s_tj[SS];     // { time, int_as_float(type*EE) }
    __shared__ float s_part[256];
    __shared__ float s_red[8];
    __shared__ int   s_last;

    const int tid = threadIdx.x;
    const int e = tid & 63;
    const int slice = tid >> 6;
    const int lane = tid & 31;
    const int w = tid >> 5;

    const float4* __restrict__ emb4 = (const float4*)emb;
    const float4* __restrict__ A4 = (const float4*)Amat;
    const float4* __restrict__ P4 = (const float4*)Pmat;
    float4* s_ap4 = (float4*)s_ap;

    if (blockIdx.x < P1_BLOCKS) {
        // ---------------- part 1: log-likelihood ----------------
        const int b = blockIdx.x >> 6;
        const int grp = blockIdx.x & 63;

        for (int j = tid; j < SS; j += 256) {
            float2 v;
            v.x = times[b * SS + j];
            v.y = __int_as_float(types[b * SS + j] * EE);
            s_tj[j] = v;
        }
        __syncthreads();

        double ll_acc = 0.0;
        const int rows[4] = {2 * grp, 2 * grp + 1, 255 - 2 * grp, 254 - 2 * grp};

        #pragma unroll
        for (int r = 0; r < 4; r++) {
            const int i = rows[r];
            const float2 tji = s_tj[i];
            const float ti = tji.x;
            const int tyio = __float_as_int(tji.y);
            const int tyi = tyio >> 6;

            // stage: ap.x = e_u*A[u,tyi,:], ap.y = -LOG2E * e_i * e_u * P[u,tyi,:]
            for (int idx4 = tid; idx4 < NTT * EE / 4; idx4 += 256) {
                const int u = idx4 >> 4;           // EE/4 = 16
                const int rm = idx4 & 15;
                const int g4 = (u * NTT + tyi) * 16 + rm;
                const float4 ev = __ldg(&emb4[idx4]);
                const float4 ki = __ldg(&emb4[tyi * 16 + rm]);
                const float4 av = __ldg(&A4[g4]);
                const float4 pv = __ldg(&P4[g4]);
                float4 lo, hi;
                lo.x = ev.x * av.x; lo.y = -LOG2E * ki.x * ev.x * pv.x;
                lo.z = ev.y * av.y; lo.w = -LOG2E * ki.y * ev.y * pv.y;
                hi.x = ev.z * av.z; hi.y = -LOG2E * ki.z * ev.z * pv.z;
                hi.z = ev.w * av.w; hi.w = -LOG2E * ki.w * ev.w * pv.w;
                s_ap4[2 * idx4] = lo;
                s_ap4[2 * idx4 + 1] = hi;
            }
            __syncthreads();

            float m0 = 0.0f, m1 = 0.0f;
            #pragma unroll 4
            for (int j = slice; j < i; j += 8) {
                const float2 tj = s_tj[j];
                const float2 ap = s_ap[__float_as_int(tj.y) + e];
                m0 = fmaf(ap.x, ex2f(ap.y * (ti - tj.x)), m0);
                const int j2 = j + 4;
                if (j2 < i) {
                    const float2 tj2 = s_tj[j2];
                    const float2 ap2 = s_ap[__float_as_int(tj2.y) + e];
                    m1 = fmaf(ap2.x, ex2f(ap2.y * (ti - tj2.x)), m1);
                }
            }
            s_part[tid] = m0 + m1;
            __syncthreads();

            if (tid < 64) {
                const float ei = __ldg(&emb[tyio + e]);
                float mt = ei * (s_part[e] + s_part[64 + e] + s_part[128 + e] + s_part[192 + e]);
                float x = fmaf(ei, __ldg(&a[tyio + e]), mt);
                float sp = softplus_f(x);
                #pragma unroll
                for (int off = 16; off > 0; off >>= 1)
                    sp += __shfl_xor_sync(0xffffffffu, sp, off);
                if (lane == 0) s_red[e >> 5] = sp;
            }
            __syncthreads();

            if (tid == 0 && ti >= 0.0f)
                ll_acc += (double)logf(s_red[0] + s_red[1] + 1e-16f);
        }
        if (tid == 0) g_ll_part[blockIdx.x] = ll_acc;
    } else {
        // ---------------- part 2: intensity at T ----------------
        const int idx2 = blockIdx.x - P1_BLOCKS;
        const int b = idx2 / NTT;
        const int k = idx2 - b * NTT;

        for (int j = tid; j < SS; j += 256) {
            float2 v;
            v.x = times[b * SS + j];
            v.y = __int_as_float(types[b * SS + j] * EE);
            s_tj[j] = v;
        }
        for (int idx4 = tid; idx4 < NTT * EE / 4; idx4 += 256) {
            const int u = idx4 >> 4;
            const int rm = idx4 & 15;
            const int g4 = (u * NTT + k) * 16 + rm;
            const float4 ev = __ldg(&emb4[idx4]);
            const float4 ki = __ldg(&emb4[k * 16 + rm]);
            const float4 av = __ldg(&A4[g4]);
            const float4 pv = __ldg(&P4[g4]);
            float4 lo, hi;
            lo.x = ev.x * av.x; lo.y = -LOG2E * ki.x * ev.x * pv.x;
            lo.z = ev.y * av.y; lo.w = -LOG2E * ki.y * ev.y * pv.y;
            hi.x = ev.z * av.z; hi.y = -LOG2E * ki.z * ev.z * pv.z;
            hi.z = ev.w * av.w; hi.w = -LOG2E * ki.w * ev.w * pv.w;
            s_ap4[2 * idx4] = lo;
            s_ap4[2 * idx4 + 1] = hi;
        }
        __syncthreads();

        const float Tf = read_T(Tp);

        float m0 = 0.0f, m1 = 0.0f;
        #pragma unroll 4
        for (int i = slice; i < SS; i += 8) {
            const float2 tj = s_tj[i];
            if (tj.x >= 0.0f) {
                const float2 ap = s_ap[__float_as_int(tj.y) + e];
                m0 = fmaf(ap.x, ex2f(ap.y * (Tf - tj.x)), m0);
            }
            const float2 tj2 = s_tj[i + 4];
            if (tj2.x >= 0.0f) {
                const float2 ap2 = s_ap[__float_as_int(tj2.y) + e];
                m1 = fmaf(ap2.x, ex2f(ap2.y * (Tf - tj2.x)), m1);
            }
        }
        s_part[tid] = m0 + m1;
        __syncthreads();

        if (tid < 64) {
            const float ek = __ldg(&emb[k * EE + e]);
            float m = ek * (s_part[e] + s_part[64 + e] + s_part[128 + e] + s_part[192 + e]);
            float x = fmaf(ek, __ldg(&a[k * EE + e]), m);
            float sp = softplus_f(x);
            #pragma unroll
            for (int off = 16; off > 0; off >>= 1)
                sp += __shfl_xor_sync(0xffffffffu, sp, off);
            if (lane == 0) s_red[e >> 5] = sp;
        }
        __syncthreads();

        if (tid == 0) g_int_part[idx2] = s_red[0] + s_red[1];
    }

    // ---------------- last block finishes ----------------
    if (tid == 0) {
        __threadfence();
        unsigned ticket = atomicAdd(&g_count, 1u);
        s_last = (ticket == GRID - 1);
    }
    __syncthreads();
    if (!s_last) return;

    // base_sum partials (deterministic tree)
    {
        float ps = 0.0f;
        for (int idx = tid; idx < NTT * EE; idx += 256)
            ps += softplus_f(emb[idx] * a[idx]);
        #pragma unroll
        for (int off = 16; off > 0; off >>= 1)
            ps += __shfl_xor_sync(0xffffffffu, ps, off);
        if (lane == 0) s_red[w] = ps;
    }

    // ll sum: 512 doubles
    __shared__ double s_dll[8];
    {
        double d = g_ll_part[tid] + g_ll_part[tid + 256];
        #pragma unroll
        for (int off = 16; off > 0; off >>= 1)
            d += __shfl_xor_sync(0xffffffffu, d, off);
        if (lane == 0) s_dll[w] = d;
    }

    // per-batch intensity-at-T sum + first/last/any scan (warp per batch)
    __shared__ float s_int[BB], s_first[BB], s_last_t[BB];
    __shared__ int s_any[BB];
    {
        float iv = 0.0f;
        if (lane < NTT) iv += g_int_part[w * NTT + lane];
        if (lane + 32 < NTT) iv += g_int_part[w * NTT + lane + 32];
        float mn = 1e30f, mx = -1e30f;
        int any = 0;
        #pragma unroll
        for (int mloop = 0; mloop < SS / 32; mloop++) {
            float t = times[w * SS + lane + 32 * mloop];
            if (t >= 0.0f) { any = 1; mn = fminf(mn, t); mx = fmaxf(mx, t); }
        }
        #pragma unroll
        for (int off = 16; off > 0; off >>= 1) {
            iv += __shfl_xor_sync(0xffffffffu, iv, off);
            mn = fminf(mn, __shfl_xor_sync(0xffffffffu, mn, off));
            mx = fmaxf(mx, __shfl_xor_sync(0xffffffffu, mx, off));
            any |= __shfl_xor_sync(0xffffffffu, any, off);
        }
        if (lane == 0) {
            s_int[w] = iv;
            s_any[w] = any;
            s_first[w] = any ? mn : 0.0f;
            s_last_t[w] = any ? mx : 0.0f;
        }
    }
    __syncthreads();

    if (tid == 0) {
        float base_sum = 0.0f;
        double ll = 0.0;
        #pragma unroll
        for (int ww = 0; ww < 8; ww++) { base_sum += s_red[ww]; ll += s_dll[ww]; }
        const float Tf = read_T(Tp);
        double integral = 0.0;
        for (int b = 0; b < BB; b++) {
            float ib;
            if (s_any[b]) ib = s_int[b] * (Tf - s_last_t[b]) + base_sum * s_first[b];
            else          ib = base_sum * Tf;
            integral += (double)ib;
        }
        out[0] = (float)(-(ll - integral));
        g_count = 0;   // reset for next graph replay (deterministic)
    }
}

extern "C" void kernel_launch(void* const* d_in, const int* in_sizes, int n_in,
                              void* d_out, int out_size) {
    const float* times = (const float*)d_in[0];
    const int*   types = (const int*)d_in[1];
    const void*  Tp    = d_in[2];
    const float* emb   = (const float*)d_in[3];
    const float* a     = (const float*)d_in[4];
    const float* Amat  = (const float*)d_in[5];
    const float* Pmat  = (const float*)d_in[6];
    float* out = (float*)d_out;

    body_k<<<GRID, 256>>>(times, types, emb, a, Amat, Pmat, Tp, out);
}